// round 9
// baseline (speedup 1.0000x reference)
#include <cuda_runtime.h>
#include <math.h>
#include <stdint.h>
#include <cuda_fp16.h>

#define KCODES 512
#define DIM 64
#define NROWS 262144
#define ROWS_PER_CTA 128
#define NBLOCKS (NROWS / ROWS_PER_CTA)   // 2048
#define TPB 256
#define MARGIN 1e-4f

#define WCH 68                            // words per code in W plane buffers
#define PLANE_WORDS (64 * WCH)            // 4352
#define BUF_WORDS (2 * PLANE_WORDS)       // hi + lo
#define SDP 520                           // s_dist stride in halves
#define DIST_HALVES (ROWS_PER_CTA * SDP)  // 66560
#define DIST_BYTES (DIST_HALVES * 2)      // 133120
#define DYN_SMEM (DIST_BYTES + 2 * BUF_WORDS * 4)   // 133120 + 69632 = 202752

// Scratch (no device-side allocation allowed)
__device__ float  g_sw[KCODES];
__device__ int    g_counts[KCODES];
__device__ double g_partial[NBLOCKS];
__device__ float  g_whi[KCODES * DIM];    // tf32(w)
__device__ float  g_wlo[KCODES * DIM];    // tf32(w - tf32(w))

__device__ __forceinline__ uint32_t smem_u32(const void* p) {
    uint32_t a;
    asm("{ .reg .u64 t; cvta.to.shared.u64 t, %1; cvt.u32.u64 %0, t; }" : "=r"(a) : "l"(p));
    return a;
}
__device__ __forceinline__ uint32_t to_tf32(float f) {
    uint32_t r;
    asm("cvt.rna.tf32.f32 %0, %1;" : "=r"(r) : "f"(f));
    return r;
}
__device__ __forceinline__ void mma1688(float& c0, float& c1, float& c2, float& c3,
                                        uint32_t a0, uint32_t a1, uint32_t a2, uint32_t a3,
                                        uint32_t b0, uint32_t b1) {
    asm volatile("mma.sync.aligned.m16n8k8.row.col.f32.tf32.tf32.f32 "
                 "{%0,%1,%2,%3}, {%4,%5,%6,%7}, {%8,%9}, {%0,%1,%2,%3};"
                 : "+f"(c0), "+f"(c1), "+f"(c2), "+f"(c3)
                 : "r"(a0), "r"(a1), "r"(a2), "r"(a3), "r"(b0), "r"(b1));
}
__device__ __forceinline__ void cpasync16(uint32_t saddr, const void* g) {
    asm volatile("cp.async.cg.shared.global [%0], [%1], 16;" :: "r"(saddr), "l"(g) : "memory");
}

// ---------------------------------------------------------------------------
// Kernel 1: code norms (exact R2 association) + tf32 hi/lo split + hist zero
// ---------------------------------------------------------------------------
__global__ void vq_prep(const float* __restrict__ W) {
    int k = blockIdx.x * 64 + threadIdx.x;   // 8 x 64
    const float* w = W + (size_t)k * DIM;
    float s = 0.0f;
    #pragma unroll
    for (int d = 0; d < DIM; ++d) {
        float v = w[d];
        s += v * v;
        uint32_t hb = to_tf32(v);
        float hf = __uint_as_float(hb);
        uint32_t lb = to_tf32(v - hf);
        g_whi[k * DIM + d] = hf;
        g_wlo[k * DIM + d] = __uint_as_float(lb);
    }
    g_sw[k] = s;
    g_counts[k] = 0;
}

// ---------------------------------------------------------------------------
// Kernel 2: 3xTF32 mma.sync scoring -> fp16 dist -> prune -> exact re-rank
// Output: out[0]=loss | out[1..1+N*64)=q_st | out[1+N*64]=perp | idx (float)
// ---------------------------------------------------------------------------
extern "C" __global__ void __launch_bounds__(TPB, 1)
vq_main(const float* __restrict__ X, const float* __restrict__ W,
        float* __restrict__ out) {
    extern __shared__ char dynsm[];
    __half* s_dist = (__half*)dynsm;                         // [128][520]
    float*  s_wf   = (float*)(dynsm + DIST_BYTES);           // 2 bufs x (hi|lo)
    __shared__ float  s_sw[KCODES];
    __shared__ double s_red[TPB];

    const int tid  = threadIdx.x;
    const int lane = tid & 31;
    const int warp = tid >> 5;
    const int g    = lane >> 2;      // row group 0..7
    const int tl   = lane & 3;       // k-dim group 0..3
    const int rowBase = blockIdx.x * ROWS_PER_CTA;

    for (int i = tid; i < KCODES; i += TPB) s_sw[i] = g_sw[i];

    const uint32_t swbase = smem_u32(s_wf);

    // prefetch chunk 0: hi + lo planes (64 codes x 64 dims each)
    {
        const float4* ghi = (const float4*)g_whi;
        const float4* glo = (const float4*)g_wlo;
        for (int i = tid; i < 1024; i += TPB) {
            int code = i >> 4, d4 = i & 15;
            uint32_t off = (uint32_t)(code * WCH + d4 * 4) * 4;
            cpasync16(swbase + off, ghi + i);
            cpasync16(swbase + PLANE_WORDS * 4 + off, glo + i);
        }
        asm volatile("cp.async.commit_group;" ::: "memory");
    }

    // A fragments: 16 rows x 64 dims per warp, hi/lo tf32 split, registers
    uint32_t ah[8][4], al[8][4];
    {
        const float* xr0 = X + (size_t)(rowBase + warp * 16 + g) * DIM;
        const float* xr8 = xr0 + 8 * DIM;
        #pragma unroll
        for (int s = 0; s < 8; ++s) {
            float v;
            v = xr0[8 * s + tl];
            ah[s][0] = to_tf32(v); al[s][0] = to_tf32(v - __uint_as_float(ah[s][0]));
            v = xr8[8 * s + tl];
            ah[s][1] = to_tf32(v); al[s][1] = to_tf32(v - __uint_as_float(ah[s][1]));
            v = xr0[8 * s + tl + 4];
            ah[s][2] = to_tf32(v); al[s][2] = to_tf32(v - __uint_as_float(ah[s][2]));
            v = xr8[8 * s + tl + 4];
            ah[s][3] = to_tf32(v); al[s][3] = to_tf32(v - __uint_as_float(ah[s][3]));
        }
    }

    const int drow = warp * 16 + g;

    // ---- chunk loop: 8 chunks of 64 codes, double-buffered hi/lo planes ----
    for (int c = 0; c < 8; ++c) {
        const int buf = c & 1;
        asm volatile("cp.async.wait_group 0;" ::: "memory");
        __syncthreads();
        if (c < 7) {
            const float4* ghi = (const float4*)(g_whi + (size_t)(c + 1) * 64 * DIM);
            const float4* glo = (const float4*)(g_wlo + (size_t)(c + 1) * 64 * DIM);
            uint32_t dstb = swbase + (uint32_t)((buf ^ 1) * BUF_WORDS) * 4;
            for (int i = tid; i < 1024; i += TPB) {
                int code = i >> 4, d4 = i & 15;
                uint32_t off = (uint32_t)(code * WCH + d4 * 4) * 4;
                cpasync16(dstb + off, ghi + i);
                cpasync16(dstb + PLANE_WORDS * 4 + off, glo + i);
            }
            asm volatile("cp.async.commit_group;" ::: "memory");
        }

        const float* wh = s_wf + buf * BUF_WORDS;
        const float* wl = wh + PLANE_WORDS;

        float acc[8][4];
        #pragma unroll
        for (int t = 0; t < 8; ++t)
            acc[t][0] = acc[t][1] = acc[t][2] = acc[t][3] = 0.0f;

        #pragma unroll
        for (int s = 0; s < 8; ++s) {
            #pragma unroll
            for (int t = 0; t < 8; ++t) {
                const int wo = (t * 8 + g) * WCH + 8 * s + tl;   // conflict-free (4g+tl)
                uint32_t bh0 = __float_as_uint(wh[wo]);
                uint32_t bh1 = __float_as_uint(wh[wo + 4]);
                uint32_t bl0 = __float_as_uint(wl[wo]);
                uint32_t bl1 = __float_as_uint(wl[wo + 4]);
                // small terms first, main last
                mma1688(acc[t][0], acc[t][1], acc[t][2], acc[t][3],
                        ah[s][0], ah[s][1], ah[s][2], ah[s][3], bl0, bl1);
                mma1688(acc[t][0], acc[t][1], acc[t][2], acc[t][3],
                        al[s][0], al[s][1], al[s][2], al[s][3], bh0, bh1);
                mma1688(acc[t][0], acc[t][1], acc[t][2], acc[t][3],
                        ah[s][0], ah[s][1], ah[s][2], ah[s][3], bh0, bh1);
            }
        }

        // r = sw_k - 2*dot  -> fp16 dist cache
        #pragma unroll
        for (int t = 0; t < 8; ++t) {
            const int k0 = c * 64 + t * 8 + 2 * tl;
            float r0 = fmaf(acc[t][0], -2.0f, s_sw[k0]);
            float r1 = fmaf(acc[t][1], -2.0f, s_sw[k0 + 1]);
            float r2 = fmaf(acc[t][2], -2.0f, s_sw[k0]);
            float r3 = fmaf(acc[t][3], -2.0f, s_sw[k0 + 1]);
            *(__half2*)&s_dist[(size_t)drow * SDP + k0]       = __floats2half2_rn(r0, r1);
            *(__half2*)&s_dist[(size_t)(drow + 8) * SDP + k0] = __floats2half2_rn(r2, r3);
        }
    }
    __syncthreads();

    // ---- scan: 2 threads per row (256 codes each) ----
    const int row  = tid >> 1;
    const int half = tid & 1;
    const int rowG = rowBase + row;
    const uint4* du = (const uint4*)(s_dist + (size_t)row * SDP + half * 256);

    float minr = __int_as_float(0x7f800000);
    #pragma unroll 4
    for (int j = 0; j < 32; ++j) {           // 32 x uint4 = 256 halves
        uint4 u = du[j];
        __half2 h0 = *(__half2*)&u.x, h1 = *(__half2*)&u.y;
        __half2 h2 = *(__half2*)&u.z, h3 = *(__half2*)&u.w;
        float2 f0 = __half22float2(h0), f1 = __half22float2(h1);
        float2 f2 = __half22float2(h2), f3 = __half22float2(h3);
        minr = fminf(minr, fminf(fminf(fminf(f0.x, f0.y), fminf(f1.x, f1.y)),
                                 fminf(fminf(f2.x, f2.y), fminf(f3.x, f3.y))));
    }
    float om = __shfl_xor_sync(0xffffffffu, minr, 1);
    const float cutoff = fminf(minr, om) + MARGIN;

    int cnt = 0;
    int ck[8] = {0, 0, 0, 0, 0, 0, 0, 0};
    for (int j = 0; j < 32; ++j) {
        uint4 u = du[j];
        const uint32_t uw[4] = {u.x, u.y, u.z, u.w};
        #pragma unroll
        for (int q = 0; q < 4; ++q) {
            float2 f = __half22float2(*(__half2*)&uw[q]);
            if (f.x < cutoff) { if (cnt < 8) ck[cnt] = half * 256 + j * 8 + q * 2;     cnt++; }
            if (f.y < cutoff) { if (cnt < 8) ck[cnt] = half * 256 + j * 8 + q * 2 + 1; cnt++; }
        }
    }
    int ocnt = __shfl_xor_sync(0xffffffffu, cnt, 1);
    int ock[8];
    #pragma unroll
    for (int i = 0; i < 8; ++i) ock[i] = __shfl_xor_sync(0xffffffffu, ck[i], 1);
    const bool over = (cnt > 8) || (ocnt > 8);

    int bestIdx = 0;
    if (half == 0) {
        // exact comparator (R2 association, proven flip-free vs reference)
        float4 x[16];
        const float4* xp = (const float4*)(X + (size_t)rowG * DIM);
        #pragma unroll
        for (int gg = 0; gg < 16; ++gg) x[gg] = xp[gg];
        float sx = 0.0f;
        #pragma unroll
        for (int gg = 0; gg < 16; ++gg) {
            sx += x[gg].x * x[gg].x; sx += x[gg].y * x[gg].y;
            sx += x[gg].z * x[gg].z; sx += x[gg].w * x[gg].w;
        }
        float bestDist = __int_as_float(0x7f800000);

        #define EXACT_CHECK(kk) {                                              \
            const int k_ = (kk);                                               \
            const float4* wp = (const float4*)(W + (size_t)k_ * DIM);          \
            float dot = 0.0f;                                                  \
            _Pragma("unroll")                                                  \
            for (int gg = 0; gg < 16; ++gg) {                                  \
                float4 w4 = __ldg(wp + gg);                                    \
                dot += x[gg].x * w4.x; dot += x[gg].y * w4.y;                  \
                dot += x[gg].z * w4.z; dot += x[gg].w * w4.w;                  \
            }                                                                  \
            float tt = sx + s_sw[k_];                                          \
            float dist = tt - 2.0f * dot;                                      \
            if (dist < bestDist) { bestDist = dist; bestIdx = k_; }            \
        }

        if (over) {
            for (int k = 0; k < KCODES; ++k) EXACT_CHECK(k);
        } else {
            for (int i = 0; i < cnt; ++i)  EXACT_CHECK(ck[i]);   // k<256, ascending
            for (int i = 0; i < ocnt; ++i) EXACT_CHECK(ock[i]);  // k>=256, ascending
        }
        #undef EXACT_CHECK

        out[2 + (size_t)NROWS * DIM + rowG] = (float)bestIdx;
        atomicAdd(&g_counts[bestIdx], 1);
    }
    bestIdx = __shfl_sync(0xffffffffu, bestIdx, lane & ~1);

    // ---- q_st + loss: each half writes its 32 dims (4B-aligned -> scalar STG)
    double lsum = 0.0;
    {
        const float4* qp  = (const float4*)(W + (size_t)bestIdx * DIM + half * 32);
        const float4* xp2 = (const float4*)(X + (size_t)rowG * DIM + half * 32);
        float* op = out + 1 + (size_t)rowG * DIM + half * 32;
        #pragma unroll
        for (int gg = 0; gg < 8; ++gg) {
            float4 q4 = __ldg(qp + gg);
            float4 xv = xp2[gg];
            float e;
            e = q4.x - xv.x; op[4*gg + 0] = xv.x + e; lsum += (double)(e * e);
            e = q4.y - xv.y; op[4*gg + 1] = xv.y + e; lsum += (double)(e * e);
            e = q4.z - xv.z; op[4*gg + 2] = xv.z + e; lsum += (double)(e * e);
            e = q4.w - xv.w; op[4*gg + 3] = xv.w + e; lsum += (double)(e * e);
        }
    }

    s_red[tid] = lsum;
    __syncthreads();
    for (int s = TPB / 2; s > 0; s >>= 1) {
        if (tid < s) s_red[tid] += s_red[tid + s];
        __syncthreads();
    }
    if (tid == 0) g_partial[blockIdx.x] = s_red[0];
}

// ---------------------------------------------------------------------------
__global__ void vq_finalize(float* __restrict__ out) {
    __shared__ double sd[512];
    __shared__ float  sf[512];
    const int t = threadIdx.x;  // 512 threads

    double v = 0.0;
    for (int i = t; i < NBLOCKS; i += 512) v += g_partial[i];
    sd[t] = v;

    float c = (float)g_counts[t] / (float)NROWS;
    sf[t] = c * logf(c + 1e-10f);
    __syncthreads();

    for (int s = 256; s > 0; s >>= 1) {
        if (t < s) { sd[t] += sd[t + s]; sf[t] += sf[t + s]; }
        __syncthreads();
    }
    if (t == 0) {
        float m = (float)(sd[0] / ((double)NROWS * (double)DIM));
        out[0] = m + 0.25f * m;
        out[1 + (size_t)NROWS * DIM] = expf(-sf[0]) / (float)KCODES;
    }
}

// ---------------------------------------------------------------------------
extern "C" void kernel_launch(void* const* d_in, const int* in_sizes, int n_in,
                              void* d_out, int out_size) {
    const float* X = (const float*)d_in[0];   // inputs  [N, 64]
    const float* W = (const float*)d_in[1];   // emb_weight [512, 64]
    float* out = (float*)d_out;

    cudaFuncSetAttribute((const void*)vq_main,
                         cudaFuncAttributeMaxDynamicSharedMemorySize, DYN_SMEM);

    vq_prep<<<KCODES / 64, 64>>>(W);
    vq_main<<<NBLOCKS, TPB, DYN_SMEM>>>(X, W, out);
    vq_finalize<<<1, KCODES>>>(out);
}